// round 15
// baseline (speedup 1.0000x reference)
#include <cuda_runtime.h>
#include <math.h>

#define KSEL   20
#define PARTS  8
#define NTHR   256
#define SEG    256
#define MERGE  (PARTS * KSEL)   // 160
#define BATCH  64
#define M_OUT  180
#define ROWB   (M_OUT * 8)
#define KMAX   262143u          // 2^18 - 1
#define NMS_TH 0.05f

__device__ unsigned long long g_top[BATCH][PARTS][KSEL];
__device__ int4 g_meta[BATCH][PARTS];
__device__ int  g_done[BATCH];

__device__ __forceinline__ void pf_l2(const void* p) {
    asm volatile("prefetch.global.L2 [%0];" :: "l"(p));
}

// Pack survivor: higher score first, then smaller (level,idx). Invalid (<=0.15) -> score bits 0.
__device__ __forceinline__ unsigned long long mkpack(float logit, int key) {
    float sc = 1.0f / (1.0f + expf(-logit));
    unsigned sb = (sc > 0.15f) ? __float_as_uint(sc) : 0u;
    return ((unsigned long long)sb << 18) | (unsigned long long)(KMAX - (unsigned)key);
}

// ---- warp-aggregated push into local smem pool (FULL-WARP convergent calls only) ----
__device__ __forceinline__ void push1_l(float v, int key, bool pred,
                                        int* cnt, unsigned long long* pool, int cap) {
    unsigned mask = __ballot_sync(0xffffffffu, pred);
    if (mask) {
        int lane = threadIdx.x & 31;
        int leader = __ffs(mask) - 1;
        int base = 0;
        if (lane == leader) base = atomicAdd(cnt, __popc(mask));
        base = __shfl_sync(0xffffffffu, base, leader);
        if (pred) {
            int pos = base + __popc(mask & ((1u << lane) - 1u));
            if (pos < cap) pool[pos] = mkpack(v, key);
        }
    }
}
__device__ __forceinline__ void push4_l(float4 v, int key, float T,
                                        int* cnt, unsigned long long* pool, int cap) {
    float m = fmaxf(fmaxf(v.x, v.y), fmaxf(v.z, v.w));
    if (__any_sync(0xffffffffu, m > T)) {
        push1_l(v.x, key + 0, v.x > T, cnt, pool, cap);
        push1_l(v.y, key + 1, v.y > T, cnt, pool, cap);
        push1_l(v.z, key + 2, v.z > T, cnt, pool, cap);
        push1_l(v.w, key + 3, v.w > T, cnt, pool, cap);
    }
}

__global__ __launch_bounds__(NTHR, 4)
void detpost_kernel(const float* __restrict__ cls0, const float* __restrict__ shp0, const float* __restrict__ off0,
                    const float* __restrict__ cls1, const float* __restrict__ shp1, const float* __restrict__ off1,
                    const float* __restrict__ cls2, const float* __restrict__ shp2, const float* __restrict__ off2,
                    float* __restrict__ out)
{
    const int b    = blockIdx.x >> 3;
    const int part = blockIdx.x & 7;
    const int tid  = threadIdx.x;

    __shared__ unsigned long long sp[SEG];
    __shared__ unsigned long long s_loc20[KSEL];
    __shared__ unsigned long long s_merge[MERGE];
    __shared__ int4 s_mmeta[PARTS];
    __shared__ int s_cnt;
    __shared__ int s_clvl[3];
    __shared__ int s_last;
    __shared__ unsigned long long s_selp[KSEL];
    __shared__ float    s_ext[KSEL][7];
    __shared__ int      s_vld[KSEL];
    __shared__ unsigned s_supp[KSEL];
    __shared__ unsigned s_kept;

    const float4* p0 = (const float4*)(cls0 + (size_t)b * 32768);
    const float4* p1 = (const float4*)(cls1 + (size_t)b * 4096);
    const float4* p2 = (const float4*)(cls2 + (size_t)b * 512);

    if (tid == 0) s_cnt = 0;
    if (tid < KSEL) { s_loc20[tid] = 0ull; s_selp[tid] = 0ull; }
    if (tid < 3) s_clvl[tid] = 0;
    __syncthreads();

    const float T0 = 2.90f, T1 = 2.25f, T2 = 1.30f;

    // ---------------- Phase 1: balanced 1/8 scan (front-batched loads) ----------------
    // part p: L0 [p*1024,(p+1)*1024) f4 (4/thread)
    //         + L1 eighth (warps 0-3, full warps)
    //         + L2 eighth (warp 0 FULL, lanes>=16 sentinel)  <- fixed R14 deadlock
    {
        const int q = part * 1024;
        float4 r[4];
        #pragma unroll
        for (int u = 0; u < 4; u++) r[u] = p0[q + u * NTHR + tid];
        float4 e1;
        int l1i = part * 128 + tid;
        if (tid < 128) e1 = p1[l1i];
        float4 e2 = make_float4(-1e30f, -1e30f, -1e30f, -1e30f);
        int l2i = part * 16 + (tid & 15);          // clamped: always a valid index
        if (tid < 16) e2 = p2[l2i];
        #pragma unroll
        for (int u = 0; u < 4; u++)
            push4_l(r[u], (q + u * NTHR + tid) * 4, T0, &s_cnt, sp, SEG);
        if (tid < 128)   // warps 0..3, full warps
            push4_l(e1, (1 << 16) | (l1i * 4), T1, &s_cnt, sp, SEG);
        if (tid < 32)    // warp 0, FULL warp; lanes 16..31 have all-false predicates
            push4_l(e2, (2 << 16) | (l2i * 4), T2, &s_cnt, sp, SEG);
    }
    __syncthreads();

    // ---------------- Phase 2: local counts + local exact top-20 ----------------
    const int tot = s_cnt;
    const int n   = min(tot, SEG);
    {
        int t = tid;
        bool have = (t < n);
        int lvl = 3;
        if (have) {
            unsigned long long p = sp[t];
            lvl = ((int)(KMAX - (unsigned)(p & (unsigned long long)KMAX))) >> 16;
            int r = 0, j = 0;
            for (; j + 4 <= n; j += 4) {
                r += (sp[j]   > p); r += (sp[j+1] > p);
                r += (sp[j+2] > p); r += (sp[j+3] > p);
            }
            for (; j < n; j++) r += (sp[j] > p);
            if (r < KSEL) s_loc20[r] = p;
        }
        unsigned b0 = __ballot_sync(0xffffffffu, have && lvl == 0);
        unsigned b1 = __ballot_sync(0xffffffffu, have && lvl == 1);
        unsigned b2 = __ballot_sync(0xffffffffu, have && lvl == 2);
        if ((tid & 31) == 0) {
            if (b0) atomicAdd(&s_clvl[0], __popc(b0));
            if (b1) atomicAdd(&s_clvl[1], __popc(b1));
            if (b2) atomicAdd(&s_clvl[2], __popc(b2));
        }
    }
    __syncthreads();

    // ---------------- Phase 2.5: L2-prefetch box data for local top-20 ----------------
    if (tid < KSEL) {
        unsigned long long p = s_loc20[tid];
        if (p != 0ull) {
            int key = (int)(KMAX - (unsigned)(p & (unsigned long long)KMAX));
            int l = key >> 16, idx = key & 0xffff;
            if (l <= 2) {
                int S = (l == 0) ? 32 : ((l == 1) ? 16 : 8);
                int N = S * S * S;
                const float* shp = (l == 0) ? shp0 : ((l == 1) ? shp1 : shp2);
                const float* off = (l == 0) ? off0 : ((l == 1) ? off1 : off2);
                size_t base = (size_t)b * 3 * N + idx;
                pf_l2(off + base);
                pf_l2(off + base + (size_t)N);
                pf_l2(off + base + 2 * (size_t)N);
                pf_l2(shp + base);
                pf_l2(shp + base + (size_t)N);
                pf_l2(shp + base + 2 * (size_t)N);
            }
        }
    }

    // ---------------- Phase 3: publish + arrive ----------------
    if (tid < KSEL) g_top[b][part][tid] = s_loc20[tid];
    if (tid == 0)   g_meta[b][part] = make_int4(tot, s_clvl[0], s_clvl[1], s_clvl[2]);
    __threadfence();
    __syncthreads();
    if (tid == 0) s_last = (atomicAdd(&g_done[b], 1) == PARTS - 1) ? 1 : 0;
    __syncthreads();

    // part 7: static -1 fill for rows 20..179 (independent of merge)
    if (part == PARTS - 1) {
        float4* o4 = (float4*)(out + (size_t)b * ROWB + KSEL * 8);
        const float4 neg = make_float4(-1.f, -1.f, -1.f, -1.f);
        for (int e = tid; e < (M_OUT - KSEL) * 2; e += NTHR)
            o4[e] = neg;
    }
    if (!s_last) return;

    // ---------------- Phase 4 (last arriver): merge 160 -> top-20 ----------------
    if (tid == 0) g_done[b] = 0;   // reset for next graph replay (all arrivals done)
    if (tid < MERGE) s_merge[tid] = g_top[b][tid / KSEL][tid % KSEL];
    if (tid < PARTS) s_mmeta[tid] = g_meta[b][tid];
    __syncthreads();
    if (tid < MERGE) {
        unsigned long long p = s_merge[tid];
        if (p != 0ull) {
            int r = 0;
            #pragma unroll 8
            for (int j = 0; j < MERGE; j++) r += (s_merge[j] > p);
            if (r < KSEL) s_selp[r] = p;
        }
    }
    __syncthreads();

    bool hot;
    {
        int c0 = 0, c1 = 0, c2 = 0; bool capok = true;
        #pragma unroll
        for (int s = 0; s < PARTS; s++) {
            int4 m = s_mmeta[s];
            capok = capok && (m.x <= SEG);
            c0 += m.y; c1 += m.z; c2 += m.w;
        }
        hot = capok && (c0 >= KSEL) && (c1 >= KSEL) && (c2 >= KSEL);
    }

    if (!hot) {
        // Cold fallback: solo adaptive full rescan (statistically unreachable).
        float T[3] = {T0, T1, T2};
        const float4* ps[3] = {p0, p1, p2};
        const int nf4[3] = {8192, 1024, 128};
        __shared__ int s_snap[3];
        __shared__ unsigned long long sp2[1024];
        int total = 0;
        for (int attempt = 0; attempt < 32; attempt++) {
            if (tid == 0) s_cnt = 0;
            __syncthreads();
            #pragma unroll
            for (int l = 0; l < 3; l++) {
                // nf4[l] is a multiple of NTHR or cuts on warp boundaries:
                // 8192/1024: all threads iterate; 128: threads 0..127 = warps 0..3 full.
                for (int i4 = tid; i4 < nf4[l]; i4 += NTHR) {
                    float4 v = ps[l][i4];
                    push4_l(v, (l << 16) | (i4 * 4), T[l], &s_cnt, sp2, 1024);
                }
                __syncthreads();
                if (tid == 0) s_snap[l] = s_cnt;
                __syncthreads();
            }
            int cc[3];
            cc[0] = s_snap[0]; cc[1] = s_snap[1] - s_snap[0]; cc[2] = s_snap[2] - s_snap[1];
            total = s_snap[2];
            bool ok = (total <= 1024) && (cc[0] >= KSEL) && (cc[1] >= KSEL) && (cc[2] >= KSEL);
            if (ok) break;
            #pragma unroll
            for (int l = 0; l < 3; l++) {
                if (cc[l] < KSEL) T[l] = fmaxf(T[l] - 0.75f, -1.7f);
                else if (total > 1024 && cc[l] > 4 * KSEL) T[l] += 0.4f;
            }
            __syncthreads();
        }
        total = min(total, 1024);
        if (tid < KSEL) s_selp[tid] = 0ull;
        __syncthreads();
        for (int t = tid; t < total; t += NTHR) {
            unsigned long long p = sp2[t];
            int r = 0, j = 0;
            for (; j + 4 <= total; j += 4) {
                r += (sp2[j]   > p); r += (sp2[j+1] > p);
                r += (sp2[j+2] > p); r += (sp2[j+3] > p);
            }
            for (; j < total; j++) r += (sp2[j] > p);
            if (r < KSEL) s_selp[r] = p;
        }
        __syncthreads();
    }

    if (tid >= 32) return;
    const int lane = tid;

    // ---------------- Phase 5: decode 20 candidates (L2-warm) ----------------
    float sc = 0.f, cz = 0.f, cy = 0.f, cx = 0.f, d0 = 0.f, d1 = 0.f, d2 = 0.f;
    int myvalid = 0;
    if (lane < KSEL) {
        unsigned long long p = s_selp[lane];
        sc = __uint_as_float((unsigned)(p >> 18));
        int key = (int)(KMAX - (unsigned)(p & (unsigned long long)KMAX));
        int l = key >> 16, idx = key & 0xffff;
        myvalid = ((p >> 18) != 0ull) ? 1 : 0;
        if (p != 0ull && l <= 2) {
            int S = (l == 0) ? 32 : ((l == 1) ? 16 : 8);
            int N = S * S * S;
            float stride = 128.0f / (float)S;
            int z = idx / (S * S);
            int rem = idx - z * S * S;
            int y = rem / S;
            int x = rem - y * S;
            const float* shp = (l == 0) ? shp0 : ((l == 1) ? shp1 : shp2);
            const float* off = (l == 0) ? off0 : ((l == 1) ? off1 : off2);
            size_t base = (size_t)b * 3 * N;
            cz = ((float)z + off[base + 0 * (size_t)N + idx]) * stride;
            cy = ((float)y + off[base + 1 * (size_t)N + idx]) * stride;
            cx = ((float)x + off[base + 2 * (size_t)N + idx]) * stride;
            d0 = shp[base + 0 * (size_t)N + idx];
            d1 = shp[base + 1 * (size_t)N + idx];
            d2 = shp[base + 2 * (size_t)N + idx];
        }
        float sz0 = fmaxf(d0, 0.f), sz1 = fmaxf(d1, 0.f), sz2 = fmaxf(d2, 0.f);
        s_ext[lane][0] = cz - 0.5f * sz0;
        s_ext[lane][1] = cy - 0.5f * sz1;
        s_ext[lane][2] = cx - 0.5f * sz2;
        s_ext[lane][3] = cz + 0.5f * sz0;
        s_ext[lane][4] = cy + 0.5f * sz1;
        s_ext[lane][5] = cx + 0.5f * sz2;
        s_ext[lane][6] = sz0 * sz1 * sz2;
        s_vld[lane] = myvalid;
    }
    __syncwarp();

    // ---------------- Phase 6a: parallel suppressor masks ----------------
    if (lane < KSEL) {
        float lz = s_ext[lane][0], ly = s_ext[lane][1], lx = s_ext[lane][2];
        float hz = s_ext[lane][3], hy = s_ext[lane][4], hx = s_ext[lane][5];
        float vol = s_ext[lane][6];
        unsigned m = 0;
        #pragma unroll 4
        for (int j = 0; j < KSEL; j++) {
            float iz = fminf(hz, s_ext[j][3]) - fmaxf(lz, s_ext[j][0]);
            float iy = fminf(hy, s_ext[j][4]) - fmaxf(ly, s_ext[j][1]);
            float ix = fminf(hx, s_ext[j][5]) - fmaxf(lx, s_ext[j][2]);
            float inter = fmaxf(iz, 0.f) * fmaxf(iy, 0.f) * fmaxf(ix, 0.f);
            float iou = inter / (s_ext[j][6] + vol - inter + 1e-8f);
            if (j < lane && iou > NMS_TH) m |= (1u << j);
        }
        s_supp[lane] = m;
    }
    __syncwarp();

    // ---------------- Phase 6b: greedy resolution on bitmasks ----------------
    if (lane == 0) {
        unsigned kept = 0;
        #pragma unroll
        for (int i = 0; i < KSEL; i++) {
            bool kp = (s_vld[i] != 0) && ((s_supp[i] & kept) == 0u);
            kept |= (kp ? 1u : 0u) << i;
        }
        s_kept = kept;
    }
    __syncwarp();
    unsigned kept = s_kept;

    // ---------------- Phase 7: write rows 0..19 ----------------
    if (lane < KSEL && ((kept >> lane) & 1u)) {
        int r = __popc(kept & ((1u << lane) - 1u));
        float4* o4 = (float4*)(out + (size_t)b * ROWB + (size_t)r * 8);
        o4[0] = make_float4(1.0f, sc, cz, cy);
        o4[1] = make_float4(cx, d0, d1, d2);
    }
    {
        int kc = __popc(kept);
        const float4 neg = make_float4(-1.f, -1.f, -1.f, -1.f);
        for (int r = kc + lane; r < KSEL; r += 32) {
            float4* o4 = (float4*)(out + (size_t)b * ROWB + (size_t)r * 8);
            o4[0] = neg; o4[1] = neg;
        }
    }
}

extern "C" void kernel_launch(void* const* d_in, const int* in_sizes, int n_in,
                              void* d_out, int out_size) {
    detpost_kernel<<<BATCH * PARTS, NTHR>>>(
        (const float*)d_in[0], (const float*)d_in[1], (const float*)d_in[2],
        (const float*)d_in[3], (const float*)d_in[4], (const float*)d_in[5],
        (const float*)d_in[6], (const float*)d_in[7], (const float*)d_in[8],
        (float*)d_out);
}

// round 16
// speedup vs baseline: 1.0171x; 1.0171x over previous
#include <cuda_runtime.h>
#include <math.h>

#define KSEL   20
#define SEG    512          // per-rank local survivor pool
#define MERGE  (4 * KSEL)   // 80 merged candidates at rank 0
#define M_OUT  180
#define ROWB   (M_OUT * 8)
#define KMAX   262143u      // 2^18 - 1
#define NMS_TH 0.05f

__device__ __forceinline__ unsigned smem_u32(const void* p) {
    return (unsigned)__cvta_generic_to_shared(p);
}
__device__ __forceinline__ unsigned mapa0(unsigned addr) {
    unsigned r;
    asm("mapa.shared::cluster.u32 %0, %1, %2;" : "=r"(r) : "r"(addr), "r"(0));
    return r;
}
__device__ __forceinline__ unsigned my_ctarank() {
    unsigned r; asm("mov.u32 %0, %%cluster_ctarank;" : "=r"(r)); return r;
}
__device__ __forceinline__ void st_cluster_u64(unsigned addr, unsigned long long v) {
    asm volatile("st.relaxed.cluster.shared::cluster.u64 [%0], %1;" :: "r"(addr), "l"(v) : "memory");
}
__device__ __forceinline__ void st_cluster_u32(unsigned addr, unsigned v) {
    asm volatile("st.relaxed.cluster.shared::cluster.u32 [%0], %1;" :: "r"(addr), "r"(v) : "memory");
}
__device__ __forceinline__ void fence_cluster() {
    asm volatile("fence.acq_rel.cluster;" ::: "memory");
}
__device__ __forceinline__ void pf_l2(const void* p) {
    asm volatile("prefetch.global.L2 [%0];" :: "l"(p));
}

// Pack survivor: higher score first, then smaller (level,idx). Invalid (<=0.15) -> score bits 0.
__device__ __forceinline__ unsigned long long mkpack(float logit, int key) {
    float sc = 1.0f / (1.0f + expf(-logit));
    unsigned sb = (sc > 0.15f) ? __float_as_uint(sc) : 0u;
    return ((unsigned long long)sb << 18) | (unsigned long long)(KMAX - (unsigned)key);
}

// ---- warp-aggregated push into local smem pool (full-warp convergent calls only) ----
__device__ __forceinline__ void push1_l(float v, int key, bool pred,
                                        int* cnt, unsigned long long* pool, int cap) {
    unsigned mask = __ballot_sync(0xffffffffu, pred);
    if (mask) {
        int lane = threadIdx.x & 31;
        int leader = __ffs(mask) - 1;
        int base = 0;
        if (lane == leader) base = atomicAdd(cnt, __popc(mask));
        base = __shfl_sync(0xffffffffu, base, leader);
        if (pred) {
            int pos = base + __popc(mask & ((1u << lane) - 1u));
            if (pos < cap) pool[pos] = mkpack(v, key);
        }
    }
}
__device__ __forceinline__ void push4_l(float4 v, int key, float T,
                                        int* cnt, unsigned long long* pool, int cap) {
    float m = fmaxf(fmaxf(v.x, v.y), fmaxf(v.z, v.w));
    if (__any_sync(0xffffffffu, m > T)) {
        push1_l(v.x, key + 0, v.x > T, cnt, pool, cap);
        push1_l(v.y, key + 1, v.y > T, cnt, pool, cap);
        push1_l(v.z, key + 2, v.z > T, cnt, pool, cap);
        push1_l(v.w, key + 3, v.w > T, cnt, pool, cap);
    }
}

__global__ __launch_bounds__(512, 2) __cluster_dims__(4, 1, 1)
void detpost_kernel(const float* __restrict__ cls0, const float* __restrict__ shp0, const float* __restrict__ off0,
                    const float* __restrict__ cls1, const float* __restrict__ shp1, const float* __restrict__ off1,
                    const float* __restrict__ cls2, const float* __restrict__ shp2, const float* __restrict__ off2,
                    float* __restrict__ out)
{
    const int b    = blockIdx.x >> 2;
    const unsigned rank = my_ctarank();
    const int tid  = threadIdx.x;

    __shared__ unsigned long long sp[SEG];        // local survivor pool
    __shared__ unsigned long long s_loc20[KSEL];  // local top-20
    __shared__ unsigned long long s_merge[MERGE]; // rank0: 4x20 merged candidates
    __shared__ int s_cnt;
    __shared__ int s_clvl[3];                     // local per-level counts
    __shared__ int s_mcnt[4][3];                  // rank0: per-rank per-level counts
    __shared__ int s_flag[4];                     // rank0: per-rank arrival flags (= tot+1)
    __shared__ unsigned long long s_selp[KSEL];
    __shared__ float    s_ext[KSEL][7];
    __shared__ int      s_vld[KSEL];
    __shared__ unsigned s_supp[KSEL];
    __shared__ unsigned s_kept;

    const float4* p0 = (const float4*)(cls0 + (size_t)b * 32768);
    const float4* p1 = (const float4*)(cls1 + (size_t)b * 4096);
    const float4* p2 = (const float4*)(cls2 + (size_t)b * 512);

    // flags zeroed in the very first instructions; remote writes arrive >= one
    // scan-latency later (cluster CTAs are co-scheduled), so no init race.
    if (tid < 4) s_flag[tid] = 0;
    if (tid == 0) s_cnt = 0;
    if (tid < KSEL) { s_loc20[tid] = 0ull; s_selp[tid] = 0ull; }
    if (tid < 3) s_clvl[tid] = 0;
    __syncthreads();

    const float T0 = 2.90f, T1 = 2.25f, T2 = 1.30f;

    // ---------------- Phase 1: balanced 4-way split scan into LOCAL pools ----------------
    // every rank: L0 quarter (4 f4/thread) + L1 quarter (tid<256) + L2 slice (tid<32)
    {
        const int q = (int)rank * 2048;
        float4 r[4];
        #pragma unroll
        for (int u = 0; u < 4; u++) r[u] = p0[q + u * 512 + tid];
        float4 e1, e2;
        int l1i = (int)rank * 256 + tid;      // L1 quarter
        int l2i = (int)rank * 32 + tid;       // L2 slice
        if (tid < 256) e1 = p1[l1i];
        if (tid < 32)  e2 = p2[l2i];

        // rank 3: fire-and-forget -1 fill for rows 20..179 (fully off critical path)
        if (rank == 3 && tid < (M_OUT - KSEL) * 2) {
            float4* o4 = (float4*)(out + (size_t)b * ROWB + KSEL * 8);
            o4[tid] = make_float4(-1.f, -1.f, -1.f, -1.f);
        }

        #pragma unroll
        for (int u = 0; u < 4; u++)
            push4_l(r[u], (q + u * 512 + tid) * 4, T0, &s_cnt, sp, SEG);
        if (tid < 256) push4_l(e1, (1 << 16) | (l1i * 4), T1, &s_cnt, sp, SEG);
        if (tid < 32)  push4_l(e2, (2 << 16) | (l2i * 4), T2, &s_cnt, sp, SEG);
    }
    __syncthreads();

    // ---------------- Phase 2: local per-level counts + local exact top-20 ----------------
    const int tot = s_cnt;
    const int n   = min(tot, SEG);
    {
        int t = tid;
        bool have = (t < n);
        int lvl = 3;
        if (have) {
            unsigned long long p = sp[t];
            lvl = ((int)(KMAX - (unsigned)(p & (unsigned long long)KMAX))) >> 16;
            int r = 0, j = 0;
            for (; j + 4 <= n; j += 4) {
                r += (sp[j]   > p); r += (sp[j+1] > p);
                r += (sp[j+2] > p); r += (sp[j+3] > p);
            }
            for (; j < n; j++) r += (sp[j] > p);
            if (r < KSEL) s_loc20[r] = p;
        }
        unsigned b0 = __ballot_sync(0xffffffffu, have && lvl == 0);
        unsigned b1 = __ballot_sync(0xffffffffu, have && lvl == 1);
        unsigned b2 = __ballot_sync(0xffffffffu, have && lvl == 2);
        if ((tid & 31) == 0) {
            if (b0) atomicAdd(&s_clvl[0], __popc(b0));
            if (b1) atomicAdd(&s_clvl[1], __popc(b1));
            if (b2) atomicAdd(&s_clvl[2], __popc(b2));
        }
    }
    __syncthreads();

    // ---------------- Phase 2.5: L2-prefetch box data for local top-20 ----------------
    if (tid < KSEL) {
        unsigned long long p = s_loc20[tid];
        if (p != 0ull) {
            int key = (int)(KMAX - (unsigned)(p & (unsigned long long)KMAX));
            int l = key >> 16, idx = key & 0xffff;
            if (l <= 2) {
                int S = (l == 0) ? 32 : ((l == 1) ? 16 : 8);
                int N = S * S * S;
                const float* shp = (l == 0) ? shp0 : ((l == 1) ? shp1 : shp2);
                const float* off = (l == 0) ? off0 : ((l == 1) ? off1 : off2);
                size_t base = (size_t)b * 3 * N + idx;
                pf_l2(off + base);
                pf_l2(off + base + (size_t)N);
                pf_l2(off + base + 2 * (size_t)N);
                pf_l2(shp + base);
                pf_l2(shp + base + (size_t)N);
                pf_l2(shp + base + 2 * (size_t)N);
            }
        }
    }

    // ---------------- Phase 3: handoff ----------------
    if (rank != 0) {
        // ship payload to rank 0 (relaxed DSMEM stores)
        if (tid < KSEL)
            st_cluster_u64(mapa0(smem_u32(&s_merge[rank * KSEL + tid])), s_loc20[tid]);
        if (tid == 0) {
            st_cluster_u32(mapa0(smem_u32(&s_mcnt[rank][0])), (unsigned)s_clvl[0]);
            st_cluster_u32(mapa0(smem_u32(&s_mcnt[rank][1])), (unsigned)s_clvl[1]);
            st_cluster_u32(mapa0(smem_u32(&s_mcnt[rank][2])), (unsigned)s_clvl[2]);
        }
        __syncthreads();                       // all payload stores issued (intra-CTA hb)
        if (tid == 0) {
            fence_cluster();                   // cumulative release of payload at cluster scope
            st_cluster_u32(mapa0(smem_u32(&s_flag[rank])), (unsigned)tot + 1u);
        }
        return;                                // no wait: remotes are done
    }

    // rank 0: own contribution + poll for 3 remote flags
    if (tid < KSEL) s_merge[tid] = s_loc20[tid];
    if (tid == 0) {
        s_mcnt[0][0] = s_clvl[0]; s_mcnt[0][1] = s_clvl[1]; s_mcnt[0][2] = s_clvl[2];
        s_flag[0] = tot + 1;
        volatile int* vf = (volatile int*)s_flag;
        while (vf[1] == 0) { }
        while (vf[2] == 0) { }
        while (vf[3] == 0) { }
        fence_cluster();                       // acquire: payload visible to this CTA
    }
    __syncthreads();

    // ---------------- Phase 4: merge-select over 80 + hot check ----------------
    if (tid < MERGE) {
        unsigned long long p = s_merge[tid];
        if (p != 0ull) {
            int r = 0;
            #pragma unroll
            for (int j = 0; j < MERGE; j++) r += (s_merge[j] > p);
            if (r < KSEL) s_selp[r] = p;
        }
    }
    __syncthreads();

    bool hot;
    {
        int c0 = s_mcnt[0][0] + s_mcnt[1][0] + s_mcnt[2][0] + s_mcnt[3][0];
        int c1 = s_mcnt[0][1] + s_mcnt[1][1] + s_mcnt[2][1] + s_mcnt[3][1];
        int c2 = s_mcnt[0][2] + s_mcnt[1][2] + s_mcnt[2][2] + s_mcnt[3][2];
        bool capok = (s_flag[0] <= SEG + 1) && (s_flag[1] <= SEG + 1) &&
                     (s_flag[2] <= SEG + 1) && (s_flag[3] <= SEG + 1);
        hot = capok && (c0 >= KSEL) && (c1 >= KSEL) && (c2 >= KSEL);
    }

    if (!hot) {
        // Cold fallback: solo adaptive full rescan (statistically unreachable).
        float T[3] = {T0, T1, T2};
        const float4* ps[3] = {p0, p1, p2};
        const int nf4[3] = {8192, 1024, 128};
        __shared__ int s_snap[3];
        int total = 0;
        for (int attempt = 0; attempt < 32; attempt++) {
            if (tid == 0) s_cnt = 0;
            __syncthreads();
            #pragma unroll
            for (int l = 0; l < 3; l++) {
                for (int i4 = tid; i4 < nf4[l]; i4 += 512) {
                    float4 v = ps[l][i4];
                    push4_l(v, (l << 16) | (i4 * 4), T[l], &s_cnt, sp, SEG);
                }
                __syncthreads();
                if (tid == 0) s_snap[l] = s_cnt;
                __syncthreads();
            }
            int cc[3];
            cc[0] = s_snap[0]; cc[1] = s_snap[1] - s_snap[0]; cc[2] = s_snap[2] - s_snap[1];
            total = s_snap[2];
            bool ok = (total <= SEG) && (cc[0] >= KSEL) && (cc[1] >= KSEL) && (cc[2] >= KSEL);
            if (ok) break;
            #pragma unroll
            for (int l = 0; l < 3; l++) {
                if (cc[l] < KSEL) T[l] = fmaxf(T[l] - 0.75f, -1.7f);
                else if (total > SEG && cc[l] > 4 * KSEL) T[l] += 0.4f;
            }
            __syncthreads();
        }
        total = min(total, SEG);
        if (tid < KSEL) s_selp[tid] = 0ull;
        __syncthreads();
        for (int t = tid; t < total; t += 512) {
            unsigned long long p = sp[t];
            int r = 0, j = 0;
            for (; j + 4 <= total; j += 4) {
                r += (sp[j]   > p); r += (sp[j+1] > p);
                r += (sp[j+2] > p); r += (sp[j+3] > p);
            }
            for (; j < total; j++) r += (sp[j] > p);
            if (r < KSEL) s_selp[r] = p;
        }
        __syncthreads();
    }

    if (tid >= 32) return;
    const int lane = tid;

    // ---------------- Phase 5: decode 20 candidates (L2-warm after prefetch) ----------------
    float sc = 0.f, cz = 0.f, cy = 0.f, cx = 0.f, d0 = 0.f, d1 = 0.f, d2 = 0.f;
    int myvalid = 0;
    if (lane < KSEL) {
        unsigned long long p = s_selp[lane];
        sc = __uint_as_float((unsigned)(p >> 18));
        int key = (int)(KMAX - (unsigned)(p & (unsigned long long)KMAX));
        int l = key >> 16, idx = key & 0xffff;
        myvalid = ((p >> 18) != 0ull) ? 1 : 0;
        if (p != 0ull && l <= 2) {
            int S = (l == 0) ? 32 : ((l == 1) ? 16 : 8);
            int N = S * S * S;
            float stride = 128.0f / (float)S;
            int z = idx / (S * S);
            int rem = idx - z * S * S;
            int y = rem / S;
            int x = rem - y * S;
            const float* shp = (l == 0) ? shp0 : ((l == 1) ? shp1 : shp2);
            const float* off = (l == 0) ? off0 : ((l == 1) ? off1 : off2);
            size_t base = (size_t)b * 3 * N;
            cz = ((float)z + off[base + 0 * (size_t)N + idx]) * stride;
            cy = ((float)y + off[base + 1 * (size_t)N + idx]) * stride;
            cx = ((float)x + off[base + 2 * (size_t)N + idx]) * stride;
            d0 = shp[base + 0 * (size_t)N + idx];
            d1 = shp[base + 1 * (size_t)N + idx];
            d2 = shp[base + 2 * (size_t)N + idx];
        }
        float sz0 = fmaxf(d0, 0.f), sz1 = fmaxf(d1, 0.f), sz2 = fmaxf(d2, 0.f);
        s_ext[lane][0] = cz - 0.5f * sz0;
        s_ext[lane][1] = cy - 0.5f * sz1;
        s_ext[lane][2] = cx - 0.5f * sz2;
        s_ext[lane][3] = cz + 0.5f * sz0;
        s_ext[lane][4] = cy + 0.5f * sz1;
        s_ext[lane][5] = cx + 0.5f * sz2;
        s_ext[lane][6] = sz0 * sz1 * sz2;
        s_vld[lane] = myvalid;
    }
    __syncwarp();

    // ---------------- Phase 6a: parallel suppressor masks ----------------
    if (lane < KSEL) {
        float lz = s_ext[lane][0], ly = s_ext[lane][1], lx = s_ext[lane][2];
        float hz = s_ext[lane][3], hy = s_ext[lane][4], hx = s_ext[lane][5];
        float vol = s_ext[lane][6];
        unsigned m = 0;
        #pragma unroll 4
        for (int j = 0; j < KSEL; j++) {
            float iz = fminf(hz, s_ext[j][3]) - fmaxf(lz, s_ext[j][0]);
            float iy = fminf(hy, s_ext[j][4]) - fmaxf(ly, s_ext[j][1]);
            float ix = fminf(hx, s_ext[j][5]) - fmaxf(lx, s_ext[j][2]);
            float inter = fmaxf(iz, 0.f) * fmaxf(iy, 0.f) * fmaxf(ix, 0.f);
            float iou = inter / (s_ext[j][6] + vol - inter + 1e-8f);
            if (j < lane && iou > NMS_TH) m |= (1u << j);
        }
        s_supp[lane] = m;
    }
    __syncwarp();

    // ---------------- Phase 6b: greedy resolution on bitmasks ----------------
    if (lane == 0) {
        unsigned kept = 0;
        #pragma unroll
        for (int i = 0; i < KSEL; i++) {
            bool kp = (s_vld[i] != 0) && ((s_supp[i] & kept) == 0u);
            kept |= (kp ? 1u : 0u) << i;
        }
        s_kept = kept;
    }
    __syncwarp();
    unsigned kept = s_kept;

    // ---------------- Phase 7: write rows 0..19 ----------------
    if (lane < KSEL && ((kept >> lane) & 1u)) {
        int r = __popc(kept & ((1u << lane) - 1u));
        float4* o4 = (float4*)(out + (size_t)b * ROWB + (size_t)r * 8);
        o4[0] = make_float4(1.0f, sc, cz, cy);
        o4[1] = make_float4(cx, d0, d1, d2);
    }
    {
        int kc = __popc(kept);
        const float4 neg = make_float4(-1.f, -1.f, -1.f, -1.f);
        for (int r = kc + lane; r < KSEL; r += 32) {
            float4* o4 = (float4*)(out + (size_t)b * ROWB + (size_t)r * 8);
            o4[0] = neg; o4[1] = neg;
        }
    }
}

extern "C" void kernel_launch(void* const* d_in, const int* in_sizes, int n_in,
                              void* d_out, int out_size) {
    detpost_kernel<<<256, 512>>>(
        (const float*)d_in[0], (const float*)d_in[1], (const float*)d_in[2],
        (const float*)d_in[3], (const float*)d_in[4], (const float*)d_in[5],
        (const float*)d_in[6], (const float*)d_in[7], (const float*)d_in[8],
        (float*)d_out);
}

// round 17
// speedup vs baseline: 1.1577x; 1.1382x over previous
#include <cuda_runtime.h>
#include <math.h>

#define KSEL   20
#define SEG    512          // per-rank local survivor pool
#define MERGE  (4 * KSEL)   // 80 merged candidates at rank 0
#define M_OUT  180
#define ROWB   (M_OUT * 8)
#define KMAX   262143u      // 2^18 - 1
#define NMS_TH 0.05f

__device__ __forceinline__ unsigned smem_u32(const void* p) {
    return (unsigned)__cvta_generic_to_shared(p);
}
__device__ __forceinline__ unsigned mapa0(unsigned addr) {
    unsigned r;
    asm("mapa.shared::cluster.u32 %0, %1, %2;" : "=r"(r) : "r"(addr), "r"(0));
    return r;
}
__device__ __forceinline__ unsigned my_ctarank() {
    unsigned r; asm("mov.u32 %0, %%cluster_ctarank;" : "=r"(r)); return r;
}
__device__ __forceinline__ void st_cluster_u64(unsigned addr, unsigned long long v) {
    asm volatile("st.relaxed.cluster.shared::cluster.u64 [%0], %1;" :: "r"(addr), "l"(v) : "memory");
}
__device__ __forceinline__ void st_cluster_u32(unsigned addr, unsigned v) {
    asm volatile("st.relaxed.cluster.shared::cluster.u32 [%0], %1;" :: "r"(addr), "r"(v) : "memory");
}
__device__ __forceinline__ unsigned long long pack2f(float a, float b) {
    return (unsigned long long)__float_as_uint(a) | ((unsigned long long)__float_as_uint(b) << 32);
}

// Pack survivor: higher score first, then smaller (level,idx). Invalid (<=0.15) -> score bits 0.
__device__ __forceinline__ unsigned long long mkpack(float logit, int key) {
    float sc = 1.0f / (1.0f + expf(-logit));
    unsigned sb = (sc > 0.15f) ? __float_as_uint(sc) : 0u;
    return ((unsigned long long)sb << 18) | (unsigned long long)(KMAX - (unsigned)key);
}

// ---- warp-aggregated push into local smem pool (full-warp convergent calls only) ----
__device__ __forceinline__ void push1_l(float v, int key, bool pred,
                                        int* cnt, unsigned long long* pool, int cap) {
    unsigned mask = __ballot_sync(0xffffffffu, pred);
    if (mask) {
        int lane = threadIdx.x & 31;
        int leader = __ffs(mask) - 1;
        int base = 0;
        if (lane == leader) base = atomicAdd(cnt, __popc(mask));
        base = __shfl_sync(0xffffffffu, base, leader);
        if (pred) {
            int pos = base + __popc(mask & ((1u << lane) - 1u));
            if (pos < cap) pool[pos] = mkpack(v, key);
        }
    }
}
__device__ __forceinline__ void push4_l(float4 v, int key, float T,
                                        int* cnt, unsigned long long* pool, int cap) {
    float m = fmaxf(fmaxf(v.x, v.y), fmaxf(v.z, v.w));
    if (__any_sync(0xffffffffu, m > T)) {
        push1_l(v.x, key + 0, v.x > T, cnt, pool, cap);
        push1_l(v.y, key + 1, v.y > T, cnt, pool, cap);
        push1_l(v.z, key + 2, v.z > T, cnt, pool, cap);
        push1_l(v.w, key + 3, v.w > T, cnt, pool, cap);
    }
}

__global__ __launch_bounds__(512, 2) __cluster_dims__(4, 1, 1)
void detpost_kernel(const float* __restrict__ cls0, const float* __restrict__ shp0, const float* __restrict__ off0,
                    const float* __restrict__ cls1, const float* __restrict__ shp1, const float* __restrict__ off1,
                    const float* __restrict__ cls2, const float* __restrict__ shp2, const float* __restrict__ off2,
                    float* __restrict__ out)
{
    const int b    = blockIdx.x >> 2;
    const unsigned rank = my_ctarank();
    const int tid  = threadIdx.x;

    __shared__ unsigned long long sp[SEG];        // local survivor pool
    __shared__ unsigned long long s_loc20[KSEL];  // local top-20 packs
    __shared__ unsigned long long s_merge[MERGE]; // rank0: 4x20 merged packs
    __shared__ float s_mbox[MERGE][8];            // rank0: decoded rows (score,cz,cy,cx,d0,d1,d2,-)
    __shared__ int s_cnt;
    __shared__ int s_clvl[3];                     // local per-level counts
    __shared__ int s_mtot[4];                     // rank0: per-rank totals
    __shared__ int s_mcnt[4][3];                  // rank0: per-rank per-level counts
    __shared__ int s_selslot[KSEL];               // hot path: merged-slot of k-th best
    __shared__ unsigned long long s_selp[KSEL];   // cold path: packs
    __shared__ float    s_ext[KSEL][7];
    __shared__ int      s_vld[KSEL];
    __shared__ unsigned s_supp[KSEL];
    __shared__ unsigned s_kept;

    const float4* p0 = (const float4*)(cls0 + (size_t)b * 32768);
    const float4* p1 = (const float4*)(cls1 + (size_t)b * 4096);
    const float4* p2 = (const float4*)(cls2 + (size_t)b * 512);

    if (tid == 0) s_cnt = 0;
    if (tid < KSEL) { s_loc20[tid] = 0ull; s_selp[tid] = 0ull; s_selslot[tid] = -1; }
    if (tid < 3) s_clvl[tid] = 0;
    __syncthreads();

    const float T0 = 2.90f, T1 = 2.25f, T2 = 1.30f;

    // ---------------- Phase 1: balanced 4-way split scan into LOCAL pools ----------------
    {
        const int q = (int)rank * 2048;
        float4 r[4];
        #pragma unroll
        for (int u = 0; u < 4; u++) r[u] = p0[q + u * 512 + tid];
        float4 e1, e2;
        int l1i = (int)rank * 256 + tid;
        int l2i = (int)rank * 32 + tid;
        if (tid < 256) e1 = p1[l1i];
        if (tid < 32)  e2 = p2[l2i];
        #pragma unroll
        for (int u = 0; u < 4; u++)
            push4_l(r[u], (q + u * 512 + tid) * 4, T0, &s_cnt, sp, SEG);
        if (tid < 256) push4_l(e1, (1 << 16) | (l1i * 4), T1, &s_cnt, sp, SEG);
        if (tid < 32)  push4_l(e2, (2 << 16) | (l2i * 4), T2, &s_cnt, sp, SEG);
    }
    __syncthreads();

    // ---------------- Phase 2: local per-level counts + local exact top-20 ----------------
    const int tot = s_cnt;
    const int n   = min(tot, SEG);
    {
        int t = tid;
        bool have = (t < n);
        int lvl = 3;
        if (have) {
            unsigned long long p = sp[t];
            lvl = ((int)(KMAX - (unsigned)(p & (unsigned long long)KMAX))) >> 16;
            int r = 0, j = 0;
            for (; j + 4 <= n; j += 4) {
                r += (sp[j]   > p); r += (sp[j+1] > p);
                r += (sp[j+2] > p); r += (sp[j+3] > p);
            }
            for (; j < n; j++) r += (sp[j] > p);
            if (r < KSEL) s_loc20[r] = p;
        }
        unsigned b0 = __ballot_sync(0xffffffffu, have && lvl == 0);
        unsigned b1 = __ballot_sync(0xffffffffu, have && lvl == 1);
        unsigned b2 = __ballot_sync(0xffffffffu, have && lvl == 2);
        if ((tid & 31) == 0) {
            if (b0) atomicAdd(&s_clvl[0], __popc(b0));
            if (b1) atomicAdd(&s_clvl[1], __popc(b1));
            if (b2) atomicAdd(&s_clvl[2], __popc(b2));
        }
    }
    __syncthreads();

    // ---------------- Phase 2.5: PRE-BARRIER decode of local top-20 ----------------
    // Global top-20 is a subset of the union of local top-20s, so decoding here
    // moves the gather latency off rank 0's serial tail (absorbed by barrier wait).
    float dsc = 0.f, dcz = 0.f, dcy = 0.f, dcx = 0.f, dd0 = 0.f, dd1 = 0.f, dd2 = 0.f;
    if (tid < KSEL) {
        unsigned long long p = s_loc20[tid];
        dsc = __uint_as_float((unsigned)(p >> 18));
        int key = (int)(KMAX - (unsigned)(p & (unsigned long long)KMAX));
        int l = key >> 16, idx = key & 0xffff;
        if (p != 0ull && l <= 2) {
            int S = (l == 0) ? 32 : ((l == 1) ? 16 : 8);
            int N = S * S * S;
            float stride = 128.0f / (float)S;
            int z = idx / (S * S);
            int rem = idx - z * S * S;
            int y = rem / S;
            int x = rem - y * S;
            const float* shp = (l == 0) ? shp0 : ((l == 1) ? shp1 : shp2);
            const float* off = (l == 0) ? off0 : ((l == 1) ? off1 : off2);
            size_t base = (size_t)b * 3 * N;
            dcz = ((float)z + off[base + 0 * (size_t)N + idx]) * stride;
            dcy = ((float)y + off[base + 1 * (size_t)N + idx]) * stride;
            dcx = ((float)x + off[base + 2 * (size_t)N + idx]) * stride;
            dd0 = shp[base + 0 * (size_t)N + idx];
            dd1 = shp[base + 1 * (size_t)N + idx];
            dd2 = shp[base + 2 * (size_t)N + idx];
        }
    }

    // ---------------- Phase 3: ship packs + decoded rows + counts to rank 0 ----------------
    if (rank == 0) {
        if (tid < KSEL) {
            s_merge[tid] = s_loc20[tid];
            s_mbox[tid][0] = dsc; s_mbox[tid][1] = dcz; s_mbox[tid][2] = dcy; s_mbox[tid][3] = dcx;
            s_mbox[tid][4] = dd0; s_mbox[tid][5] = dd1; s_mbox[tid][6] = dd2;
        }
        if (tid == 0) {
            s_mtot[0] = tot;
            s_mcnt[0][0] = s_clvl[0]; s_mcnt[0][1] = s_clvl[1]; s_mcnt[0][2] = s_clvl[2];
        }
    } else {
        if (tid < KSEL) {
            int slot = (int)rank * KSEL + tid;
            st_cluster_u64(mapa0(smem_u32(&s_merge[slot])), s_loc20[tid]);
            unsigned baseaddr = mapa0(smem_u32(&s_mbox[slot][0]));
            st_cluster_u64(baseaddr,      pack2f(dsc, dcz));
            st_cluster_u64(baseaddr + 8,  pack2f(dcy, dcx));
            st_cluster_u64(baseaddr + 16, pack2f(dd0, dd1));
            st_cluster_u64(baseaddr + 24, pack2f(dd2, 0.f));
        }
        if (tid == 0) {
            st_cluster_u32(mapa0(smem_u32(&s_mtot[rank])), (unsigned)tot);
            st_cluster_u32(mapa0(smem_u32(&s_mcnt[rank][0])), (unsigned)s_clvl[0]);
            st_cluster_u32(mapa0(smem_u32(&s_mcnt[rank][1])), (unsigned)s_clvl[1]);
            st_cluster_u32(mapa0(smem_u32(&s_mcnt[rank][2])), (unsigned)s_clvl[2]);
        }
    }
    asm volatile("barrier.cluster.arrive.aligned;" ::: "memory");
    asm volatile("barrier.cluster.wait.aligned;"   ::: "memory");

    // ---------------- Rank 3: static -1 fill (rows 20..179); ranks 1,2 exit ----------------
    if (rank != 0) {
        if (rank == 3) {
            float4* o4 = (float4*)(out + (size_t)b * ROWB + KSEL * 8);
            const float4 neg = make_float4(-1.f, -1.f, -1.f, -1.f);
            for (int e = tid; e < (M_OUT - KSEL) * 2; e += 512)
                o4[e] = neg;
        }
        return;
    }

    // ---------------- Rank 0: merge-select over 80 (pure smem) + hot check ----------------
    if (tid < MERGE) {
        unsigned long long p = s_merge[tid];
        if (p != 0ull) {
            int r = 0;
            #pragma unroll
            for (int j = 0; j < MERGE; j++) r += (s_merge[j] > p);
            if (r < KSEL) s_selslot[r] = tid;
        }
    }
    __syncthreads();

    bool hot;
    {
        int c0 = s_mcnt[0][0] + s_mcnt[1][0] + s_mcnt[2][0] + s_mcnt[3][0];
        int c1 = s_mcnt[0][1] + s_mcnt[1][1] + s_mcnt[2][1] + s_mcnt[3][1];
        int c2 = s_mcnt[0][2] + s_mcnt[1][2] + s_mcnt[2][2] + s_mcnt[3][2];
        bool capok = (s_mtot[0] <= SEG) && (s_mtot[1] <= SEG) && (s_mtot[2] <= SEG) && (s_mtot[3] <= SEG);
        hot = capok && (c0 >= KSEL) && (c1 >= KSEL) && (c2 >= KSEL);
    }

    if (!hot) {
        // Cold fallback: solo adaptive full rescan (statistically unreachable).
        float T[3] = {T0, T1, T2};
        const float4* ps[3] = {p0, p1, p2};
        const int nf4[3] = {8192, 1024, 128};
        __shared__ int s_snap[3];
        int total = 0;
        for (int attempt = 0; attempt < 32; attempt++) {
            if (tid == 0) s_cnt = 0;
            __syncthreads();
            #pragma unroll
            for (int l = 0; l < 3; l++) {
                for (int i4 = tid; i4 < nf4[l]; i4 += 512) {
                    float4 v = ps[l][i4];
                    push4_l(v, (l << 16) | (i4 * 4), T[l], &s_cnt, sp, SEG);
                }
                __syncthreads();
                if (tid == 0) s_snap[l] = s_cnt;
                __syncthreads();
            }
            int cc[3];
            cc[0] = s_snap[0]; cc[1] = s_snap[1] - s_snap[0]; cc[2] = s_snap[2] - s_snap[1];
            total = s_snap[2];
            bool ok = (total <= SEG) && (cc[0] >= KSEL) && (cc[1] >= KSEL) && (cc[2] >= KSEL);
            if (ok) break;
            #pragma unroll
            for (int l = 0; l < 3; l++) {
                if (cc[l] < KSEL) T[l] = fmaxf(T[l] - 0.75f, -1.7f);
                else if (total > SEG && cc[l] > 4 * KSEL) T[l] += 0.4f;
            }
            __syncthreads();
        }
        total = min(total, SEG);
        if (tid < KSEL) s_selp[tid] = 0ull;
        __syncthreads();
        for (int t = tid; t < total; t += 512) {
            unsigned long long p = sp[t];
            int r = 0, j = 0;
            for (; j + 4 <= total; j += 4) {
                r += (sp[j]   > p); r += (sp[j+1] > p);
                r += (sp[j+2] > p); r += (sp[j+3] > p);
            }
            for (; j < total; j++) r += (sp[j] > p);
            if (r < KSEL) s_selp[r] = p;
        }
        __syncthreads();
    }

    if (tid >= 32) return;
    const int lane = tid;

    // ---------------- Phase 5: fetch 20 selected candidates ----------------
    float sc = 0.f, cz = 0.f, cy = 0.f, cx = 0.f, d0 = 0.f, d1 = 0.f, d2 = 0.f;
    int myvalid = 0;
    if (lane < KSEL) {
        if (hot) {
            int slot = s_selslot[lane];
            if (slot >= 0) {
                unsigned long long p = s_merge[slot];
                myvalid = ((p >> 18) != 0ull) ? 1 : 0;
                sc = s_mbox[slot][0];
                cz = s_mbox[slot][1]; cy = s_mbox[slot][2]; cx = s_mbox[slot][3];
                d0 = s_mbox[slot][4]; d1 = s_mbox[slot][5]; d2 = s_mbox[slot][6];
            }
        } else {
            unsigned long long p = s_selp[lane];
            sc = __uint_as_float((unsigned)(p >> 18));
            int key = (int)(KMAX - (unsigned)(p & (unsigned long long)KMAX));
            int l = key >> 16, idx = key & 0xffff;
            myvalid = ((p >> 18) != 0ull) ? 1 : 0;
            if (p != 0ull && l <= 2) {
                int S = (l == 0) ? 32 : ((l == 1) ? 16 : 8);
                int N = S * S * S;
                float stride = 128.0f / (float)S;
                int z = idx / (S * S);
                int rem = idx - z * S * S;
                int y = rem / S;
                int x = rem - y * S;
                const float* shp = (l == 0) ? shp0 : ((l == 1) ? shp1 : shp2);
                const float* off = (l == 0) ? off0 : ((l == 1) ? off1 : off2);
                size_t base = (size_t)b * 3 * N;
                cz = ((float)z + off[base + 0 * (size_t)N + idx]) * stride;
                cy = ((float)y + off[base + 1 * (size_t)N + idx]) * stride;
                cx = ((float)x + off[base + 2 * (size_t)N + idx]) * stride;
                d0 = shp[base + 0 * (size_t)N + idx];
                d1 = shp[base + 1 * (size_t)N + idx];
                d2 = shp[base + 2 * (size_t)N + idx];
            }
        }
        float sz0 = fmaxf(d0, 0.f), sz1 = fmaxf(d1, 0.f), sz2 = fmaxf(d2, 0.f);
        s_ext[lane][0] = cz - 0.5f * sz0;
        s_ext[lane][1] = cy - 0.5f * sz1;
        s_ext[lane][2] = cx - 0.5f * sz2;
        s_ext[lane][3] = cz + 0.5f * sz0;
        s_ext[lane][4] = cy + 0.5f * sz1;
        s_ext[lane][5] = cx + 0.5f * sz2;
        s_ext[lane][6] = sz0 * sz1 * sz2;
        s_vld[lane] = myvalid;
    }
    __syncwarp();

    // ---------------- Phase 6a: parallel suppressor masks ----------------
    if (lane < KSEL) {
        float lz = s_ext[lane][0], ly = s_ext[lane][1], lx = s_ext[lane][2];
        float hz = s_ext[lane][3], hy = s_ext[lane][4], hx = s_ext[lane][5];
        float vol = s_ext[lane][6];
        unsigned m = 0;
        #pragma unroll 4
        for (int j = 0; j < KSEL; j++) {
            float iz = fminf(hz, s_ext[j][3]) - fmaxf(lz, s_ext[j][0]);
            float iy = fminf(hy, s_ext[j][4]) - fmaxf(ly, s_ext[j][1]);
            float ix = fminf(hx, s_ext[j][5]) - fmaxf(lx, s_ext[j][2]);
            float inter = fmaxf(iz, 0.f) * fmaxf(iy, 0.f) * fmaxf(ix, 0.f);
            float iou = inter / (s_ext[j][6] + vol - inter + 1e-8f);
            if (j < lane && iou > NMS_TH) m |= (1u << j);
        }
        s_supp[lane] = m;
    }
    __syncwarp();

    // ---------------- Phase 6b: greedy resolution on bitmasks ----------------
    if (lane == 0) {
        unsigned kept = 0;
        #pragma unroll
        for (int i = 0; i < KSEL; i++) {
            bool kp = (s_vld[i] != 0) && ((s_supp[i] & kept) == 0u);
            kept |= (kp ? 1u : 0u) << i;
        }
        s_kept = kept;
    }
    __syncwarp();
    unsigned kept = s_kept;

    // ---------------- Phase 7: write rows 0..19 ----------------
    if (lane < KSEL && ((kept >> lane) & 1u)) {
        int r = __popc(kept & ((1u << lane) - 1u));
        float4* o4 = (float4*)(out + (size_t)b * ROWB + (size_t)r * 8);
        o4[0] = make_float4(1.0f, sc, cz, cy);
        o4[1] = make_float4(cx, d0, d1, d2);
    }
    {
        int kc = __popc(kept);
        const float4 neg = make_float4(-1.f, -1.f, -1.f, -1.f);
        for (int r = kc + lane; r < KSEL; r += 32) {
            float4* o4 = (float4*)(out + (size_t)b * ROWB + (size_t)r * 8);
            o4[0] = neg; o4[1] = neg;
        }
    }
}

extern "C" void kernel_launch(void* const* d_in, const int* in_sizes, int n_in,
                              void* d_out, int out_size) {
    detpost_kernel<<<256, 512>>>(
        (const float*)d_in[0], (const float*)d_in[1], (const float*)d_in[2],
        (const float*)d_in[3], (const float*)d_in[4], (const float*)d_in[5],
        (const float*)d_in[6], (const float*)d_in[7], (const float*)d_in[8],
        (float*)d_out);
}